// round 4
// baseline (speedup 1.0000x reference)
#include <cuda_runtime.h>
#include <cstdint>
#include <cstdio>

// Problem constants
#define Bq   64
#define Sq   2048
#define INq  208
#define Hq   100
#define Gq   300      // 3*H gate rows
#define OUTq 98
#define Mq   (Bq * Sq)   // 131072 rows

// ---------------------------------------------------------------------------
// Scratch (static __device__ arrays — allocation is forbidden)
// ---------------------------------------------------------------------------
__device__ float g_xg[(size_t)Mq * Gq];  // 157 MB: xg0, then reused for xg1
__device__ float g_y [(size_t)Mq * Hq];  //  52 MB: y0, then reused for y1

#define FMA2(c, a, b) \
    asm("fma.rn.f32x2 %0, %1, %2, %0;" : "+l"(c) : "l"(a), "l"(b))

// ---------------------------------------------------------------------------
// GEMM with bias: C[m][n] = bias[n] + sum_k A[m][k] * W[n][k]
// A: M x K row-major, W: N x K row-major (A @ W^T), C: M x N.
// BM=BN=128, BK=8, 256 threads, 8x8 microtile computed as 8 x (4 f32x2 pairs).
// A is stored PAIR-REPLICATED in SMEM so the (a,a) packed operand is a plain
// LDS.64/128 (no register repacking). Double-buffered, 1 barrier per K-tile.
// Requires: M % 128 == 0, K % 4 == 0.
// ---------------------------------------------------------------------------
#define BM 128
#define BN 128
#define BK 8

__global__ __launch_bounds__(256, 2) void gemm_bias(
    const float* __restrict__ A, const float* __restrict__ W,
    const float* __restrict__ bias, float* __restrict__ C,
    int N, int K)
{
    __shared__ __align__(16) float As[2][BK][2 * BM + 8];  // replicated pairs
    __shared__ __align__(16) float Ws[2][BK][BN + 8];

    const int n0  = blockIdx.x * BN;
    const int m0  = blockIdx.y * BM;
    const int tid = threadIdx.x;
    const int tx  = tid & 15;        // n microtile
    const int ty  = tid >> 4;        // m microtile

    // Loader: each thread owns one row-half: row lr, k-offset lk (float4)
    const int  lr = tid >> 1;
    const int  lk = (tid & 1) * 4;
    const float* Ap = A + (size_t)(m0 + lr) * K + lk;
    const float* Wp = W + (size_t)(n0 + lr) * K + lk;
    const bool wrow = (n0 + lr) < N;

    unsigned long long c[8][4];
#pragma unroll
    for (int i = 0; i < 8; i++)
#pragma unroll
        for (int j = 0; j < 4; j++) c[i][j] = 0ull;

    const int ntiles = (K + BK - 1) / BK;

    // tile 0 load + store (tile 0 is always fully in-bounds on k: K >= 8)
    float4 av = *(const float4*)Ap;
    float4 wv = wrow ? *(const float4*)Wp : make_float4(0.f, 0.f, 0.f, 0.f);
    {
        As[0][lk + 0][2 * lr] = av.x; As[0][lk + 0][2 * lr + 1] = av.x;
        As[0][lk + 1][2 * lr] = av.y; As[0][lk + 1][2 * lr + 1] = av.y;
        As[0][lk + 2][2 * lr] = av.z; As[0][lk + 2][2 * lr + 1] = av.z;
        As[0][lk + 3][2 * lr] = av.w; As[0][lk + 3][2 * lr + 1] = av.w;
        Ws[0][lk + 0][lr] = wv.x; Ws[0][lk + 1][lr] = wv.y;
        Ws[0][lk + 2][lr] = wv.z; Ws[0][lk + 3][lr] = wv.w;
    }
    __syncthreads();

    for (int tile = 0; tile < ntiles; tile++) {
        const int buf = tile & 1;
        // prefetch next tile into regs (guard tail: K%8 may be 4)
        const bool more = (tile + 1) < ntiles;
        if (more) {
            const int k = (tile + 1) * BK + lk;
            const bool kv = k < K;   // K%4==0 so k<K implies k+3<K
            av = kv ? *(const float4*)(Ap + (tile + 1) * BK)
                    : make_float4(0.f, 0.f, 0.f, 0.f);
            wv = (kv && wrow) ? *(const float4*)(Wp + (tile + 1) * BK)
                              : make_float4(0.f, 0.f, 0.f, 0.f);
        }

#pragma unroll
        for (int kk = 0; kk < BK; kk++) {
            const ulonglong2* wsp = (const ulonglong2*)&Ws[buf][kk][tx * 8];
            const ulonglong2 b01 = wsp[0];
            const ulonglong2 b23 = wsp[1];
            const ulonglong2* asp = (const ulonglong2*)&As[buf][kk][ty * 16];
            const ulonglong2 a01 = asp[0];
            const ulonglong2 a23 = asp[1];
            const ulonglong2 a45 = asp[2];
            const ulonglong2 a67 = asp[3];
            unsigned long long a[8] = { a01.x, a01.y, a23.x, a23.y,
                                        a45.x, a45.y, a67.x, a67.y };
            unsigned long long bb[4] = { b01.x, b01.y, b23.x, b23.y };
#pragma unroll
            for (int i = 0; i < 8; i++)
#pragma unroll
                for (int jp = 0; jp < 4; jp++)
                    FMA2(c[i][jp], a[i], bb[jp]);
        }

        if (more) {
            // safe: buf^1 was last READ at tile-1; a barrier has passed since.
            const int nb = buf ^ 1;
            As[nb][lk + 0][2 * lr] = av.x; As[nb][lk + 0][2 * lr + 1] = av.x;
            As[nb][lk + 1][2 * lr] = av.y; As[nb][lk + 1][2 * lr + 1] = av.y;
            As[nb][lk + 2][2 * lr] = av.z; As[nb][lk + 2][2 * lr + 1] = av.z;
            As[nb][lk + 3][2 * lr] = av.w; As[nb][lk + 3][2 * lr + 1] = av.w;
            Ws[nb][lk + 0][lr] = wv.x; Ws[nb][lk + 1][lr] = wv.y;
            Ws[nb][lk + 2][lr] = wv.z; Ws[nb][lk + 3][lr] = wv.w;
            __syncthreads();
        }
    }

#pragma unroll
    for (int i = 0; i < 8; i++) {
        const size_t m = (size_t)m0 + ty * 8 + i;
#pragma unroll
        for (int jp = 0; jp < 4; jp++) {
            const int n = n0 + tx * 8 + 2 * jp;
            float lo, hi;
            asm("mov.b64 {%0, %1}, %2;" : "=f"(lo), "=f"(hi) : "l"(c[i][jp]));
            if (n < N)     C[m * N + n]     = lo + bias[n];
            if (n + 1 < N) C[m * N + n + 1] = hi + bias[n + 1];
        }
    }
}

// ---------------------------------------------------------------------------
// GRU recurrence, fused single-barrier version. One CTA per batch element
// (64 CTAs). 640 threads = 20 warps. Lane layout inside each warp:
//   jj = lane/6 (0..4), sub = lane%6; lanes 30,31 duplicate (4,0)/(4,1).
//   hidden unit j = warp*5 + jj; gate = sub/2 (r,z,n); K-half = sub&1.
// All 6 lanes of a j live in ONE warp, so the K-half combine AND the
// r/z/n gather for the gate math are warp shuffles — no second barrier.
// xg is prefetched THREE steps ahead through a register pipeline into a
// double-buffered SMEM stage, hiding DRAM latency (~577cyc) under 2 steps.
// ---------------------------------------------------------------------------
__global__ __launch_bounds__(640, 1) void gru_rec(
    const float* __restrict__ xg,     // [B][S][300] precomputed input gates (+b_ih)
    const float* __restrict__ w_hh,   // [300][100]
    const float* __restrict__ b_hh,   // [300]
    const float* __restrict__ h0,     // [B][100] (this layer's slice)
    float* __restrict__ y)            // [B][S][100]
{
    __shared__ __align__(8) float h_s[2][104];
    __shared__ float xg_s[2][304];

    const int b    = blockIdx.x;
    const int tid  = threadIdx.x;
    const int lane = tid & 31;
    const int w    = tid >> 5;        // 0..19

    int jj = lane / 6;                // 0..5
    const int sub = lane % 6;
    if (jj == 5) jj = 4;              // lanes 30,31 duplicate (4,0)/(4,1) — benign
    const int j    = w * 5 + jj;      // 0..99
    const int gate = sub >> 1;        // 0=r, 1=z, 2=n
    const int half = sub & 1;
    const int grow = gate * Hq + j;   // w_hh row index
    const int base = jj * 6;          // lane of this j's r/half0 thread

    // per-thread recurrent weights: 50 floats as 25 packed f32x2
    unsigned long long wp[25];
    {
        const float* wrow = w_hh + grow * Hq + half * 50;
#pragma unroll
        for (int q = 0; q < 25; q++) {
            const float a  = __ldg(wrow + 2 * q);
            const float bb = __ldg(wrow + 2 * q + 1);
            asm("mov.b64 %0, {%1, %2};" : "=l"(wp[q]) : "f"(a), "f"(bb));
        }
    }
    const float bhh = b_hh[grow];     // used only on half==0 lanes

    if (tid < Hq) h_s[0][tid] = h0[b * Hq + tid];

    const float* xg_b = xg + (size_t)b * Sq * Gq;
    float*       y_b  = y  + (size_t)b * Sq * Hq;

    // xg prefetch pipeline: stage step 0 into SMEM now; hold steps 1,2 in regs
    const bool loader = (half == 1);
    const int  gid    = grow;         // loaders cover 0..299 exactly (plus benign dup)
    float pA = 0.f, pB = 0.f;
    if (loader) {
        xg_s[0][gid] = xg_b[gid];
        pA = xg_b[Gq + gid];          // for step 1
        pB = xg_b[2 * Gq + gid];      // for step 2
    }
    __syncthreads();

    int cur = 0;
    for (int t = 0; t < Sq; t++) {
        const int tb = t & 1;

        // issue prefetch for step t+3 early (consumed 2 steps from now)
        float pC = 0.f;
        if (loader && t + 3 < Sq)
            pC = xg_b[(size_t)(t + 3) * Gq + gid];

        // matvec: hg[grow] partial over this lane's 50-wide K-half
        const unsigned long long* hp =
            (const unsigned long long*)(&h_s[cur][half * 50]);
        unsigned long long a0 = 0ull, a1 = 0ull;
#pragma unroll
        for (int q = 0; q < 25; q++) {
            if (q & 1) FMA2(a1, wp[q], hp[q]);
            else       FMA2(a0, wp[q], hp[q]);
        }
        unsigned long long asum;
        asm("add.rn.f32x2 %0, %1, %2;" : "=l"(asum) : "l"(a0), "l"(a1));
        float lo, hi;
        asm("mov.b64 {%0, %1}, %2;" : "=f"(lo), "=f"(hi) : "l"(asum));
        float acc = lo + hi;

        // combine K-halves: even-sub lane gets full dot, add b_hh
        acc += __shfl_down_sync(0xffffffffu, acc, 1);
        acc += bhh;                               // meaningful on even sub only

        // gather r/z/n partials for this j to the sub==0 lane
        const float hz = __shfl_sync(0xffffffffu, acc, base + 2);
        const float hn = __shfl_sync(0xffffffffu, acc, base + 4);

        if (sub == 0) {
            const float hr = acc;
            const float xr = xg_s[tb][j];
            const float xz = xg_s[tb][Hq + j];
            const float xn = xg_s[tb][2 * Hq + j];
            const float hprev = h_s[cur][j];
            const float r  = __fdividef(1.f, 1.f + __expf(-(xr + hr)));
            const float z  = __fdividef(1.f, 1.f + __expf(-(xz + hz)));
            const float na = xn + r * hn;
            const float e  = __expf(-2.f * fabsf(na));
            const float nt = copysignf(__fdividef(1.f - e, 1.f + e), na);
            const float hnew = (1.f - z) * nt + z * hprev;
            h_s[cur ^ 1][j] = hnew;
            y_b[(size_t)t * Hq + j] = hnew;
        }

        // stage xg for step t+1 (register loaded 2 steps ago — latency hidden)
        if (loader && t + 1 < Sq)
            xg_s[tb ^ 1][gid] = pA;
        pA = pB; pB = pC;

        cur ^= 1;
        __syncthreads();
    }
}

// ---------------------------------------------------------------------------
// Launch: 5 kernels on the default stream (graph-capturable, no allocs).
// ---------------------------------------------------------------------------
extern "C" void kernel_launch(void* const* d_in, const int* in_sizes, int n_in,
                              void* d_out, int out_size)
{
    (void)in_sizes; (void)n_in; (void)out_size;
    const float* seq     = (const float*)d_in[0];
    const float* h0      = (const float*)d_in[1];   // [2][B][H]
    const float* w_ih_l0 = (const float*)d_in[2];
    const float* w_hh_l0 = (const float*)d_in[3];
    const float* b_ih_l0 = (const float*)d_in[4];
    const float* b_hh_l0 = (const float*)d_in[5];
    const float* w_ih_l1 = (const float*)d_in[6];
    const float* w_hh_l1 = (const float*)d_in[7];
    const float* b_ih_l1 = (const float*)d_in[8];
    const float* b_hh_l1 = (const float*)d_in[9];
    const float* w_out   = (const float*)d_in[10];
    const float* b_out   = (const float*)d_in[11];
    float* out = (float*)d_out;

    float* xgbuf = nullptr;
    float* ybuf  = nullptr;
    cudaGetSymbolAddress((void**)&xgbuf, g_xg);
    cudaGetSymbolAddress((void**)&ybuf,  g_y);

    dim3 g300((Gq + BN - 1) / BN, Mq / BM);   // (3, 1024)
    dim3 gout((OUTq + BN - 1) / BN, Mq / BM); // (1, 1024)

    gemm_bias<<<g300, 256>>>(seq, w_ih_l0, b_ih_l0, xgbuf, Gq, INq);
    gru_rec  <<<Bq, 640>>>(xgbuf, w_hh_l0, b_hh_l0, h0,           ybuf);
    gemm_bias<<<g300, 256>>>(ybuf, w_ih_l1, b_ih_l1, xgbuf, Gq, Hq);
    gru_rec  <<<Bq, 640>>>(xgbuf, w_hh_l1, b_hh_l1, h0 + Bq * Hq, ybuf);
    gemm_bias<<<gout, 256>>>(ybuf, w_out, b_out, out, OUTq, Hq);
}